// round 15
// baseline (speedup 1.0000x reference)
#include <cuda_runtime.h>
#include <math.h>

#define TT 150
#define NB 8
#define VV 2048
#define CC 16
#define LL 64
#define L3 192
#define EE 32768
#define NV (NB*VV)   // 16384

typedef unsigned long long u64;

// ---------------- static device scratch (~1.3 GB .bss) ----------------
__device__ float g_xe [(size_t)TT*NV*LL];   // encoder output; later overwritten with z
__device__ float g_agg[(size_t)TT*NV*LL];   // gathered S.xe (pass-independent)
__device__ float g_hd [NV*LL];              // domain hidden (final)
__device__ float g_cz [NV*LL];              // z_D @ ode_W1[64:128] + ode_b1
__device__ float g_Wcd[LL*L3];              // W_gd @ gd_Wi
__device__ float g_Wcc[LL*L3];              // W_gc @ gc_Wi
__device__ int   g_rowptr[VV+1];
__device__ int   g_eid [EE];
__device__ int   g_cols[EE];
__device__ float g_vals[EE];

// fast gates: __expf + fast divide (abs err ~1e-6; threshold 1e-3)
__device__ __forceinline__ float fsigm(float x){
    return __fdividef(1.f, 1.f + __expf(-x));
}
__device__ __forceinline__ float ftanh(float x){
    float xc = fminf(12.f, fmaxf(-12.f, x));
    float e = __expf(2.f*xc);
    return __fdividef(e - 1.f, e + 1.f);
}

// packed fp32x2 FMA (Blackwell FFMA2 — 2x fp32 FMA throughput, bitwise == scalar)
__device__ __forceinline__ u64 f2fma(u64 a, u64 b, u64 c){
    u64 d; asm("fma.rn.f32x2 %0, %1, %2, %3;" : "=l"(d) : "l"(a), "l"(b), "l"(c)); return d;
}
__device__ __forceinline__ u64 f2dup(float x){
    u64 d; asm("mov.b64 %0, {%1, %2};" : "=l"(d) : "f"(x), "f"(x)); return d;
}
__device__ __forceinline__ float2 f2unpk(u64 v){
    float2 r; asm("mov.b64 {%0, %1}, %2;" : "=f"(r.x), "=f"(r.y) : "l"(v)); return r;
}

// ---------------- CSR build + weight folding: ONE block, deterministic ----------------
__global__ void __launch_bounds__(1024) k_csrfold(const int* __restrict__ ei,
        const float* __restrict__ attr,
        const float* __restrict__ Wgd, const float* __restrict__ Wid,
        const float* __restrict__ Wgc, const float* __restrict__ Wic){
    __shared__ int sdeg[VV];
    __shared__ int scur[VV];
    int tid = threadIdx.x;
    for (int o = tid; o < LL*L3; o += 1024){
        int i = o / L3, j = o % L3;
        float a0 = 0.f, a1 = 0.f;
        #pragma unroll
        for (int k = 0; k < LL; k++){
            a0 += Wgd[i*LL + k] * Wid[k*L3 + j];
            a1 += Wgc[i*LL + k] * Wic[k*L3 + j];
        }
        g_Wcd[o] = a0;
        g_Wcc[o] = a1;
    }
    for (int v = tid; v < VV; v += 1024) sdeg[v] = 0;
    __syncthreads();
    for (int e = tid; e < EE; e += 1024) atomicAdd(&sdeg[ei[EE+e]], 1);
    __syncthreads();
    if (tid == 0){
        int acc = 0;
        g_rowptr[0] = 0;
        for (int v = 0; v < VV; v++){ scur[v] = acc; acc += sdeg[v]; g_rowptr[v+1] = acc; }
    }
    __syncthreads();
    for (int e = tid; e < EE; e += 1024){
        int pos = atomicAdd(&scur[ei[EE+e]], 1);
        g_eid[pos] = e;
    }
    __syncthreads();
    for (int v = tid; v < VV; v += 1024){
        int s = g_rowptr[v], e = g_rowptr[v+1];
        for (int i = s+1; i < e; i++){
            int key = g_eid[i]; int k = i-1;
            while (k >= s && g_eid[k] > key){ g_eid[k+1] = g_eid[k]; k--; }
            g_eid[k+1] = key;
        }
        for (int i = s; i < e; i++){
            int id = g_eid[i];
            g_cols[i] = ei[id];
            g_vals[i] = attr[id];
        }
    }
}

// ---------------- encoder ----------------
__global__ void k_encode(const float* __restrict__ x, const float* __restrict__ W,
                         const float* __restrict__ b){
    __shared__ float xs[CC*32];
    __shared__ float Ws[CC*LL];
    __shared__ float bs[LL];
    int blk = blockIdx.x;
    int nv = blk / 5;
    int t0 = (blk % 5) * 32;
    int tid = threadIdx.x;
    for (int i = tid; i < CC*32; i += 256){
        int c = i / 32, tl = i % 32, t = t0 + tl;
        xs[c*32 + tl] = (t < TT) ? x[((size_t)nv*CC + c)*TT + t] : 0.f;
    }
    for (int i = tid; i < CC*LL; i += 256) Ws[i] = W[i];
    if (tid < LL) bs[tid] = b[tid];
    __syncthreads();
    int l = tid & 63, tg = tid >> 6;
    for (int tl = tg; tl < 32; tl += 4){
        int t = t0 + tl;
        if (t >= TT) break;
        float acc = bs[l];
        #pragma unroll
        for (int c = 0; c < CC; c++) acc += xs[c*32 + tl] * Ws[c*LL + l];
        g_xe[((size_t)t*NV + nv)*LL + l] = acc;
    }
}

// ---------------- gather only: agg = S.xe for all t ----------------
__global__ void __launch_bounds__(256) k_agg(){
    int b = blockIdx.x;
    int t   = b >> 7;
    int rem = b & 127;
    int n   = rem >> 4;
    int v0  = (rem & 15) * 128;
    int tid = threadIdx.x;
    const float* xb = g_xe  + ((size_t)t*NV + (size_t)n*VV) * LL;
    float*       ob = g_agg + ((size_t)t*NV + (size_t)n*VV + v0) * LL;
    int lane = tid & 63, rg = tid >> 6;
    for (int r = rg; r < 128; r += 4){
        int v = v0 + r;
        int s = g_rowptr[v], e = g_rowptr[v+1];
        float acc = 0.f;
        for (int idx = s; idx < e; idx++)
            acc += xb[(size_t)g_cols[idx]*LL + lane] * g_vals[idx];
        ob[(size_t)r*LL + lane] = acc;
    }
}

// ---------------- fused persistent domain scan: double-buffered, ONE sync/step --------
// grid 128 (128 rows/block), 512 threads, dyn smem 230144 (1 block/SM, single wave)
__global__ void __launch_bounds__(512) k_domscan(const float* __restrict__ Wh,
                                                 const float* __restrict__ bias){
    extern __shared__ float sm[];
    float* Wst = sm;                 // [128][192]: rows0-63 = Wh, rows64-127 = Wcd
    float* h0  = Wst + 128*L3;       // [128][64]
    float* h1  = h0 + 128*LL;        // [128][64]
    float* a0  = h1 + 128*LL;        // [128][64]
    float* a1  = a0 + 128*LL;        // [128][64]
    float* bs  = a1 + 128*LL;        // [192]
    int tid = threadIdx.x;
    int row0 = blockIdx.x * 128;
    for (int i = tid; i < (64*L3)/4; i += 512){
        ((float4*)Wst)[i]           = ((const float4*)Wh)[i];
        ((float4*)(Wst + 64*L3))[i] = ((const float4*)g_Wcd)[i];
    }
    for (int i = tid; i < 128*LL; i += 512) h0[i] = 0.f;
    if (tid < L3) bs[tid] = bias[tid];
    {
        const float4* src = (const float4*)(g_agg + (size_t)row0*LL);
        #pragma unroll
        for (int j = 0; j < 4; j++) ((float4*)a0)[tid + j*512] = src[tid + j*512];
    }
    __syncthreads();

    int r0 = (tid >> 4) * 4, c0 = (tid & 15) * 4;
    float* hc = h0; float* hn = h1; float* ac = a0; float* an = a1;

    for (int t = 0; t < TT; t++){
        // prefetch next agg tile into registers (hidden under this step's GEMM)
        float4 pf[4];
        if (t + 1 < TT){
            const float4* src = (const float4*)(g_agg + ((size_t)(t+1)*NV + row0)*LL);
            #pragma unroll
            for (int j = 0; j < 4; j++) pf[j] = src[tid + j*512];
        }

        u64 az[4][2], ar[4][2], anh[4][2], ang[4][2];
        {
            const u64* bz = (const u64*)(bs + c0);
            const u64* br = (const u64*)(bs + 64 + c0);
            const u64* bn = (const u64*)(bs + 128 + c0);
            u64 z0=bz[0], z1=bz[1], q0=br[0], q1=br[1], n0=bn[0], n1=bn[1];
            #pragma unroll
            for (int i=0;i<4;i++){ az[i][0]=z0; az[i][1]=z1; ar[i][0]=q0; ar[i][1]=q1;
                                   ang[i][0]=n0; ang[i][1]=n1; anh[i][0]=0ull; anh[i][1]=0ull; }
        }
        // part 1: h @ Wh (W rows 0..63); n-gate -> anh
        #pragma unroll 2
        for (int k0 = 0; k0 < 64; k0 += 4){
            float4 a[4];
            #pragma unroll
            for (int i=0;i<4;i++) a[i] = *(const float4*)(hc + (r0+i)*LL + k0);
            #pragma unroll
            for (int kk=0; kk<4; kk++){
                const float* wrow = Wst + (k0+kk)*L3;
                ulonglong2 wz = *(const ulonglong2*)(wrow + c0);
                ulonglong2 wr = *(const ulonglong2*)(wrow + 64 + c0);
                ulonglong2 wn = *(const ulonglong2*)(wrow + 128 + c0);
                #pragma unroll
                for (int i=0;i<4;i++){
                    float av = (kk==0)?a[i].x:(kk==1)?a[i].y:(kk==2)?a[i].z:a[i].w;
                    u64 ad = f2dup(av);
                    az [i][0]=f2fma(ad,wz.x,az [i][0]); az [i][1]=f2fma(ad,wz.y,az [i][1]);
                    ar [i][0]=f2fma(ad,wr.x,ar [i][0]); ar [i][1]=f2fma(ad,wr.y,ar [i][1]);
                    anh[i][0]=f2fma(ad,wn.x,anh[i][0]); anh[i][1]=f2fma(ad,wn.y,anh[i][1]);
                }
            }
        }
        // part 2: agg @ Wcd (W rows 64..127); n-gate -> ang
        #pragma unroll 2
        for (int k0 = 0; k0 < 64; k0 += 4){
            float4 a[4];
            #pragma unroll
            for (int i=0;i<4;i++) a[i] = *(const float4*)(ac + (r0+i)*LL + k0);
            #pragma unroll
            for (int kk=0; kk<4; kk++){
                const float* wrow = Wst + (64 + k0 + kk)*L3;
                ulonglong2 wz = *(const ulonglong2*)(wrow + c0);
                ulonglong2 wr = *(const ulonglong2*)(wrow + 64 + c0);
                ulonglong2 wn = *(const ulonglong2*)(wrow + 128 + c0);
                #pragma unroll
                for (int i=0;i<4;i++){
                    float av = (kk==0)?a[i].x:(kk==1)?a[i].y:(kk==2)?a[i].z:a[i].w;
                    u64 ad = f2dup(av);
                    az [i][0]=f2fma(ad,wz.x,az [i][0]); az [i][1]=f2fma(ad,wz.y,az [i][1]);
                    ar [i][0]=f2fma(ad,wr.x,ar [i][0]); ar [i][1]=f2fma(ad,wr.y,ar [i][1]);
                    ang[i][0]=f2fma(ad,wn.x,ang[i][0]); ang[i][1]=f2fma(ad,wn.y,ang[i][1]);
                }
            }
        }
        // NO sync: prefetch stores to an (not read this step), gates write hn (not read)
        if (t + 1 < TT){
            #pragma unroll
            for (int j = 0; j < 4; j++) ((float4*)an)[tid + j*512] = pf[j];
        }
        #pragma unroll
        for (int i=0;i<4;i++){
            int r = r0 + i;
            float2 vz0=f2unpk(az[i][0]),  vz1=f2unpk(az[i][1]);
            float2 vr0=f2unpk(ar[i][0]),  vr1=f2unpk(ar[i][1]);
            float2 vh0=f2unpk(anh[i][0]), vh1=f2unpk(anh[i][1]);
            float2 vg0=f2unpk(ang[i][0]), vg1=f2unpk(ang[i][1]);
            float zz[4]={vz0.x,vz0.y,vz1.x,vz1.y};
            float rv[4]={vr0.x,vr0.y,vr1.x,vr1.y};
            float nh[4]={vh0.x,vh0.y,vh1.x,vh1.y};
            float ng[4]={vg0.x,vg0.y,vg1.x,vg1.y};
            #pragma unroll
            for (int j=0;j<4;j++){
                float z  = fsigm(zz[j]);
                float rg = fsigm(rv[j]);
                float nn = ftanh(ng[j] + rg*nh[j]);
                float hp = hc[r*LL + c0 + j];
                hn[r*LL + c0 + j] = (1.f-z)*nn + z*hp;
            }
        }
        __syncthreads();   // hn/an writes visible before next step's GEMM reads
        float* tp;
        tp = hc; hc = hn; hn = tp;
        tp = ac; ac = an; an = tp;
    }
    for (int i = tid; i < 128*LL; i += 512) g_hd[(size_t)row0*LL + i] = hc[i];
}

// ---------------- domain MLP + cz precompute ----------------
__global__ void k_dommlp(const float* __restrict__ Wd1, const float* __restrict__ bd1,
                         const float* __restrict__ Wd2, const float* __restrict__ bd2,
                         const float* __restrict__ odeW1, const float* __restrict__ odeb1){
    extern __shared__ float sm[];
    float* W1s = sm;
    float* W2s = W1s + 4096;
    float* Wzs = W2s + 4096;
    float* hds = Wzs + 4096;
    float* t1s = hds + 1024;
    float* zDs = t1s + 1024;
    float* b1s = zDs + 1024;
    float* b2s = b1s + 64;
    float* bos = b2s + 64;
    int tid = threadIdx.x;
    int row0 = blockIdx.x * 16;
    for (int i = tid; i < 4096; i += 256){ W1s[i] = Wd1[i]; W2s[i] = Wd2[i]; Wzs[i] = odeW1[4096 + i]; }
    for (int i = tid; i < 16*LL; i += 256) hds[i] = g_hd[(size_t)row0*LL + i];
    if (tid < 64){ b1s[tid] = bd1[tid]; b2s[tid] = bd2[tid]; bos[tid] = odeb1[tid]; }
    __syncthreads();
    int j = tid & 63, rg = tid >> 6;
    for (int r = rg; r < 16; r += 4){
        float acc = b1s[j];
        #pragma unroll
        for (int k = 0; k < LL; k++) acc += hds[r*LL + k] * W1s[k*LL + j];
        t1s[r*LL + j] = ftanh(acc);
    }
    __syncthreads();
    for (int r = rg; r < 16; r += 4){
        float acc = b2s[j];
        #pragma unroll
        for (int k = 0; k < LL; k++) acc += t1s[r*LL + k] * W2s[k*LL + j];
        zDs[r*LL + j] = acc;
    }
    __syncthreads();
    for (int r = rg; r < 16; r += 4){
        float acc = bos[j];
        #pragma unroll
        for (int k = 0; k < LL; k++) acc += zDs[r*LL + k] * Wzs[k*LL + j];
        g_cz[(size_t)(row0+r)*LL + j] = acc;
    }
}

// ---------------- fused persistent correction scan: ODE + gi-GEMM + GRU, 149 steps ----
// grid 128 (128 rows/block), 512 threads, dyn smem 230400 (1 block/SM, single wave)
__global__ void __launch_bounds__(512) k_corrscan(const float* __restrict__ odeW1,
        const float* __restrict__ odeW2, const float* __restrict__ odeb2,
        const float* __restrict__ Wh, const float* __restrict__ bias){
    extern __shared__ float sm[];
    float* Wst = sm;               // [128][192]: rows0-63 = Wh, rows64-127 = Wcc
    float* W1s = Wst + 128*L3;     // [64][64]
    float* W2s = W1s + 4096;       // [64][64]
    float* hs  = W2s + 4096;       // [128][64]
    float* hos = hs  + 128*LL;     // [128][64]
    float* Xs  = hos + 128*LL;     // [128][64]  t1 buffer, then agg tile (time-shared)
    float* bs  = Xs  + 128*LL;     // [192]
    float* b2s = bs + L3;          // [64]
    int tid = threadIdx.x;
    int row0 = blockIdx.x * 128;
    for (int i = tid; i < (64*L3)/4; i += 512){
        ((float4*)Wst)[i]           = ((const float4*)Wh)[i];
        ((float4*)(Wst + 64*L3))[i] = ((const float4*)g_Wcc)[i];
    }
    for (int i = tid; i < 1024; i += 512){ ((float4*)W1s)[i] = ((const float4*)odeW1)[i];
                                           ((float4*)W2s)[i] = ((const float4*)odeW2)[i]; }
    for (int i = tid; i < (128*LL)/4; i += 512)
        ((float4*)hs)[i] = ((const float4*)(g_xe + (size_t)row0*LL))[i];   // h0 = xe[0]
    if (tid < L3) bs[tid] = bias[tid];
    if (tid < 64) b2s[tid] = odeb2[tid];
    __syncthreads();

    int p_r0 = (tid >> 3) * 2, p_c0 = (tid & 7) * 8;    // phase1/2: 2 rows x 8 cols
    int g_r0 = (tid >> 4) * 4, g_c0 = (tid & 15) * 4;   // phase3:   4 rows x 4 cols/gate
    const float* czp = g_cz + (size_t)row0 * LL;

    // cz is loop-invariant: load ONCE into registers
    float4 cz00 = __ldg((const float4*)(czp + (size_t)(p_r0+0)*LL + p_c0));
    float4 cz01 = __ldg((const float4*)(czp + (size_t)(p_r0+0)*LL + p_c0 + 4));
    float4 cz10 = __ldg((const float4*)(czp + (size_t)(p_r0+1)*LL + p_c0));
    float4 cz11 = __ldg((const float4*)(czp + (size_t)(p_r0+1)*LL + p_c0 + 4));
    float czf[2][8] = {{cz00.x,cz00.y,cz00.z,cz00.w, cz01.x,cz01.y,cz01.z,cz01.w},
                       {cz10.x,cz10.y,cz10.z,cz10.w, cz11.x,cz11.y,cz11.z,cz11.w}};

    for (int t = 1; t < TT; t++){
        // prefetch this step's agg tile into registers (hidden under phases 1-2)
        float4 pf[4];
        {
            const float4* src = (const float4*)(g_agg + ((size_t)t*NV + row0)*LL);
            #pragma unroll
            for (int j = 0; j < 4; j++) pf[j] = src[tid + j*512];
        }

        // phase1: Xs(t1) = tanh(hs @ W1 + cz)
        {
            u64 acc[2][4];
            #pragma unroll
            for (int i=0;i<2;i++){ acc[i][0]=0ull; acc[i][1]=0ull; acc[i][2]=0ull; acc[i][3]=0ull; }
            #pragma unroll 4
            for (int k0 = 0; k0 < 64; k0 += 4){
                float4 a0 = *(const float4*)(hs + (p_r0+0)*LL + k0);
                float4 a1 = *(const float4*)(hs + (p_r0+1)*LL + k0);
                #pragma unroll
                for (int kk=0; kk<4; kk++){
                    ulonglong2 wA = *(const ulonglong2*)(W1s + (k0+kk)*LL + p_c0);
                    ulonglong2 wB = *(const ulonglong2*)(W1s + (k0+kk)*LL + p_c0 + 4);
                    float v0 = (kk==0)?a0.x:(kk==1)?a0.y:(kk==2)?a0.z:a0.w;
                    float v1 = (kk==0)?a1.x:(kk==1)?a1.y:(kk==2)?a1.z:a1.w;
                    u64 d0 = f2dup(v0), d1 = f2dup(v1);
                    acc[0][0]=f2fma(d0,wA.x,acc[0][0]); acc[0][1]=f2fma(d0,wA.y,acc[0][1]);
                    acc[0][2]=f2fma(d0,wB.x,acc[0][2]); acc[0][3]=f2fma(d0,wB.y,acc[0][3]);
                    acc[1][0]=f2fma(d1,wA.x,acc[1][0]); acc[1][1]=f2fma(d1,wA.y,acc[1][1]);
                    acc[1][2]=f2fma(d1,wB.x,acc[1][2]); acc[1][3]=f2fma(d1,wB.y,acc[1][3]);
                }
            }
            #pragma unroll
            for (int i=0;i<2;i++)
                #pragma unroll
                for (int p=0;p<4;p++){
                    float2 v = f2unpk(acc[i][p]);
                    Xs[(p_r0+i)*LL + p_c0 + 2*p    ] = ftanh(v.x + czf[i][2*p  ]);
                    Xs[(p_r0+i)*LL + p_c0 + 2*p + 1] = ftanh(v.y + czf[i][2*p+1]);
                }
        }
        __syncthreads();
        // phase2: hos = hs + Xs @ W2 + b2
        {
            u64 acc[2][4];
            {
                const u64* bp = (const u64*)(b2s + p_c0);
                u64 b0=bp[0], b1=bp[1], b2v=bp[2], b3=bp[3];
                acc[0][0]=b0; acc[0][1]=b1; acc[0][2]=b2v; acc[0][3]=b3;
                acc[1][0]=b0; acc[1][1]=b1; acc[1][2]=b2v; acc[1][3]=b3;
            }
            #pragma unroll 4
            for (int k0 = 0; k0 < 64; k0 += 4){
                float4 a0 = *(const float4*)(Xs + (p_r0+0)*LL + k0);
                float4 a1 = *(const float4*)(Xs + (p_r0+1)*LL + k0);
                #pragma unroll
                for (int kk=0; kk<4; kk++){
                    ulonglong2 wA = *(const ulonglong2*)(W2s + (k0+kk)*LL + p_c0);
                    ulonglong2 wB = *(const ulonglong2*)(W2s + (k0+kk)*LL + p_c0 + 4);
                    float v0 = (kk==0)?a0.x:(kk==1)?a0.y:(kk==2)?a0.z:a0.w;
                    float v1 = (kk==0)?a1.x:(kk==1)?a1.y:(kk==2)?a1.z:a1.w;
                    u64 d0 = f2dup(v0), d1 = f2dup(v1);
                    acc[0][0]=f2fma(d0,wA.x,acc[0][0]); acc[0][1]=f2fma(d0,wA.y,acc[0][1]);
                    acc[0][2]=f2fma(d0,wB.x,acc[0][2]); acc[0][3]=f2fma(d0,wB.y,acc[0][3]);
                    acc[1][0]=f2fma(d1,wA.x,acc[1][0]); acc[1][1]=f2fma(d1,wA.y,acc[1][1]);
                    acc[1][2]=f2fma(d1,wB.x,acc[1][2]); acc[1][3]=f2fma(d1,wB.y,acc[1][3]);
                }
            }
            #pragma unroll
            for (int i=0;i<2;i++)
                #pragma unroll
                for (int p=0;p<4;p++){
                    float2 v = f2unpk(acc[i][p]);
                    int base = (p_r0+i)*LL + p_c0 + 2*p;
                    hos[base    ] = hs[base    ] + v.x;
                    hos[base + 1] = hs[base + 1] + v.y;
                }
        }
        __syncthreads();
        // store prefetched agg tile into Xs (t1 dead; phase2 readers done)
        #pragma unroll
        for (int j = 0; j < 4; j++) ((float4*)Xs)[tid + j*512] = pf[j];
        __syncthreads();
        // phase3: GRU stacked-K GEMM: A = [hos | agg], n-gate split
        u64 az[4][2], ar[4][2], anh[4][2], ang[4][2];
        {
            const u64* bz = (const u64*)(bs + g_c0);
            const u64* br = (const u64*)(bs + 64 + g_c0);
            const u64* bn = (const u64*)(bs + 128 + g_c0);
            u64 z0=bz[0], z1=bz[1], q0=br[0], q1=br[1], n0=bn[0], n1=bn[1];
            #pragma unroll
            for (int i=0;i<4;i++){ az[i][0]=z0; az[i][1]=z1; ar[i][0]=q0; ar[i][1]=q1;
                                   ang[i][0]=n0; ang[i][1]=n1; anh[i][0]=0ull; anh[i][1]=0ull; }
        }
        #pragma unroll 2
        for (int k0 = 0; k0 < 64; k0 += 4){
            float4 a[4];
            #pragma unroll
            for (int i=0;i<4;i++) a[i] = *(const float4*)(hos + (g_r0+i)*LL + k0);
            #pragma unroll
            for (int kk=0; kk<4; kk++){
                const float* wrow = Wst + (k0+kk)*L3;
                ulonglong2 wz = *(const ulonglong2*)(wrow + g_c0);
                ulonglong2 wr = *(const ulonglong2*)(wrow + 64 + g_c0);
                ulonglong2 wn = *(const ulonglong2*)(wrow + 128 + g_c0);
                #pragma unroll
                for (int i=0;i<4;i++){
                    float av = (kk==0)?a[i].x:(kk==1)?a[i].y:(kk==2)?a[i].z:a[i].w;
                    u64 ad = f2dup(av);
                    az [i][0]=f2fma(ad,wz.x,az [i][0]); az [i][1]=f2fma(ad,wz.y,az [i][1]);
                    ar [i][0]=f2fma(ad,wr.x,ar [i][0]); ar [i][1]=f2fma(ad,wr.y,ar [i][1]);
                    anh[i][0]=f2fma(ad,wn.x,anh[i][0]); anh[i][1]=f2fma(ad,wn.y,anh[i][1]);
                }
            }
        }
        #pragma unroll 2
        for (int k0 = 0; k0 < 64; k0 += 4){
            float4 a[4];
            #pragma unroll
            for (int i=0;i<4;i++) a[i] = *(const float4*)(Xs + (g_r0+i)*LL + k0);
            #pragma unroll
            for (int kk=0; kk<4; kk++){
                const float* wrow = Wst + (64 + k0 + kk)*L3;
                ulonglong2 wz = *(const ulonglong2*)(wrow + g_c0);
                ulonglong2 wr = *(const ulonglong2*)(wrow + 64 + g_c0);
                ulonglong2 wn = *(const ulonglong2*)(wrow + 128 + g_c0);
                #pragma unroll
                for (int i=0;i<4;i++){
                    float av = (kk==0)?a[i].x:(kk==1)?a[i].y:(kk==2)?a[i].z:a[i].w;
                    u64 ad = f2dup(av);
                    az [i][0]=f2fma(ad,wz.x,az [i][0]); az [i][1]=f2fma(ad,wz.y,az [i][1]);
                    ar [i][0]=f2fma(ad,wr.x,ar [i][0]); ar [i][1]=f2fma(ad,wr.y,ar [i][1]);
                    ang[i][0]=f2fma(ad,wn.x,ang[i][0]); ang[i][1]=f2fma(ad,wn.y,ang[i][1]);
                }
            }
        }
        // NO sync needed: phase3 GEMM reads hos/Xs; gates write hs/g_xe only
        #pragma unroll
        for (int i=0;i<4;i++){
            int r = g_r0 + i;
            float2 vz0=f2unpk(az[i][0]),  vz1=f2unpk(az[i][1]);
            float2 vr0=f2unpk(ar[i][0]),  vr1=f2unpk(ar[i][1]);
            float2 vh0=f2unpk(anh[i][0]), vh1=f2unpk(anh[i][1]);
            float2 vg0=f2unpk(ang[i][0]), vg1=f2unpk(ang[i][1]);
            float zz[4]={vz0.x,vz0.y,vz1.x,vz1.y};
            float rv[4]={vr0.x,vr0.y,vr1.x,vr1.y};
            float nh[4]={vh0.x,vh0.y,vh1.x,vh1.y};
            float ng[4]={vg0.x,vg0.y,vg1.x,vg1.y};
            float hn4[4];
            #pragma unroll
            for (int j=0;j<4;j++){
                float z  = fsigm(zz[j]);
                float rg = fsigm(rv[j]);
                float nn = ftanh(ng[j] + rg*nh[j]);
                float ho = hos[r*LL + g_c0 + j];
                hn4[j] = (1.f-z)*nn + z*ho;
            }
            #pragma unroll
            for (int j=0;j<4;j++) hs[r*LL + g_c0 + j] = hn4[j];
            *(float4*)(g_xe + ((size_t)t*NV + row0 + r)*LL + g_c0)
                = make_float4(hn4[0], hn4[1], hn4[2], hn4[3]);
        }
        __syncthreads();   // hs writes + Xs reads complete before next iteration
    }
}

// ---------------- decoder ----------------
__global__ void k_decode(float* __restrict__ out, const float* __restrict__ W,
                         const float* __restrict__ b){
    __shared__ float zs[32*65];
    __shared__ float Ws[LL*CC];
    __shared__ float bs[CC];
    int blk = blockIdx.x;
    int nv = blk / 5;
    int t0 = (blk % 5) * 32;
    int tid = threadIdx.x;
    for (int i = tid; i < 32*LL; i += 256){
        int tl = i >> 6, l = i & 63, t = t0 + tl;
        zs[tl*65 + l] = (t < TT) ? g_xe[((size_t)t*NV + nv)*LL + l] : 0.f;
    }
    for (int i = tid; i < LL*CC; i += 256) Ws[i] = W[i];
    if (tid < CC) bs[tid] = b[tid];
    __syncthreads();
    for (int o = tid; o < 512; o += 256){
        int c = o >> 5, tl = o & 31, t = t0 + tl;
        if (t >= TT) continue;
        float acc = bs[c];
        #pragma unroll
        for (int l = 0; l < LL; l++) acc += zs[tl*65 + l] * Ws[l*CC + c];
        out[((size_t)nv*CC + c)*TT + t] = acc;
    }
}

// ---------------- launch ----------------
extern "C" void kernel_launch(void* const* d_in, const int* in_sizes, int n_in,
                              void* d_out, int out_size){
    const float* x      = (const float*)d_in[0];
    const int*   ei     = (const int*)  d_in[1];
    const float* attr   = (const float*)d_in[2];
    const float* W_enc  = (const float*)d_in[3];
    const float* b_enc  = (const float*)d_in[4];
    const float* W_gd   = (const float*)d_in[5];
    const float* gd_Wi  = (const float*)d_in[6];
    const float* gd_Wh  = (const float*)d_in[7];
    const float* gd_b   = (const float*)d_in[8];
    const float* W_dom1 = (const float*)d_in[9];
    const float* b_dom1 = (const float*)d_in[10];
    const float* W_dom2 = (const float*)d_in[11];
    const float* b_dom2 = (const float*)d_in[12];
    const float* ode_W1 = (const float*)d_in[13];
    const float* ode_b1 = (const float*)d_in[14];
    const float* ode_W2 = (const float*)d_in[15];
    const float* ode_b2 = (const float*)d_in[16];
    const float* W_gc   = (const float*)d_in[17];
    const float* gc_Wi  = (const float*)d_in[18];
    const float* gc_Wh  = (const float*)d_in[19];
    const float* gc_b   = (const float*)d_in[20];
    const float* W_dec  = (const float*)d_in[21];
    const float* b_dec  = (const float*)d_in[22];
    float* out = (float*)d_out;

    const int SM_DOMS  = (128*L3 + 4*128*LL + L3) * 4;                         // 230144
    const int SM_CORRS = (128*L3 + 4096 + 4096 + 3*128*LL + L3 + 64) * 4;      // 230400
    const int SM_MLP   = (3*4096 + 3*1024 + 3*64) * 4;                         // 62208

    cudaFuncSetAttribute(k_domscan,  cudaFuncAttributeMaxDynamicSharedMemorySize, SM_DOMS);
    cudaFuncSetAttribute(k_corrscan, cudaFuncAttributeMaxDynamicSharedMemorySize, SM_CORRS);
    cudaFuncSetAttribute(k_dommlp,   cudaFuncAttributeMaxDynamicSharedMemorySize, SM_MLP);

    // 1: CSR build + weight folding (one block)
    k_csrfold<<<1, 1024>>>(ei, attr, W_gd, gd_Wi, W_gc, gc_Wi);
    // 2: encoder
    k_encode<<<NV*5, 256>>>(x, W_enc, b_enc);
    // 3: gather ONCE (pass-independent)
    k_agg <<<TT*128, 256>>>();
    // 4: fused persistent domain scan (double-buffered, 1 sync/step)  <-- ncu capture slot
    k_domscan<<<NV/128, 512, SM_DOMS>>>(gd_Wh, gd_b);
    // 5: domain MLP + cz
    k_dommlp<<<NV/16, 256, SM_MLP>>>(W_dom1, b_dom1, W_dom2, b_dom2, ode_W1, ode_b1);
    // 6: fused persistent correction scan (ODE + gi-GEMM + GRU)
    k_corrscan<<<NV/128, 512, SM_CORRS>>>(ode_W1, ode_W2, ode_b2, gc_Wh, gc_b);
    // 7: decoder
    k_decode<<<NV*5, 256>>>(out, W_dec, b_dec);
}

// round 16
// speedup vs baseline: 1.0442x; 1.0442x over previous
#include <cuda_runtime.h>
#include <math.h>

#define TT 150
#define NB 8
#define VV 2048
#define CC 16
#define LL 64
#define L3 192
#define EE 32768
#define NV (NB*VV)   // 16384

typedef unsigned long long u64;

// ---------------- static device scratch (~1.3 GB .bss) ----------------
__device__ float g_xe [(size_t)TT*NV*LL];   // encoder output; later overwritten with z
__device__ float g_agg[(size_t)TT*NV*LL];   // gathered S.xe (pass-independent)
__device__ float g_hd [NV*LL];              // domain hidden (final)
__device__ float g_cz [NV*LL];              // z_D @ ode_W1[64:128] + ode_b1
__device__ float g_Wcd[LL*L3];              // W_gd @ gd_Wi
__device__ float g_Wcc[LL*L3];              // W_gc @ gc_Wi
__device__ int   g_rowptr[VV+1];
__device__ int   g_eid [EE];
__device__ int   g_cols[EE];
__device__ float g_vals[EE];

// fast gates: __expf + fast divide (abs err ~1e-6; threshold 1e-3)
__device__ __forceinline__ float fsigm(float x){
    return __fdividef(1.f, 1.f + __expf(-x));
}
__device__ __forceinline__ float ftanh(float x){
    float xc = fminf(12.f, fmaxf(-12.f, x));
    float e = __expf(2.f*xc);
    return __fdividef(e - 1.f, e + 1.f);
}

// packed fp32x2 FMA (Blackwell FFMA2 — 2x fp32 FMA throughput, bitwise == scalar)
__device__ __forceinline__ u64 f2fma(u64 a, u64 b, u64 c){
    u64 d; asm("fma.rn.f32x2 %0, %1, %2, %3;" : "=l"(d) : "l"(a), "l"(b), "l"(c)); return d;
}
__device__ __forceinline__ u64 f2dup(float x){
    u64 d; asm("mov.b64 %0, {%1, %2};" : "=l"(d) : "f"(x), "f"(x)); return d;
}
__device__ __forceinline__ float2 f2unpk(u64 v){
    float2 r; asm("mov.b64 {%0, %1}, %2;" : "=f"(r.x), "=f"(r.y) : "l"(v)); return r;
}

// ---------------- CSR build + weight folding: ONE block, deterministic ----------------
__global__ void __launch_bounds__(1024) k_csrfold(const int* __restrict__ ei,
        const float* __restrict__ attr,
        const float* __restrict__ Wgd, const float* __restrict__ Wid,
        const float* __restrict__ Wgc, const float* __restrict__ Wic){
    __shared__ int sdeg[VV];
    __shared__ int scur[VV];
    int tid = threadIdx.x;
    for (int o = tid; o < LL*L3; o += 1024){
        int i = o / L3, j = o % L3;
        float a0 = 0.f, a1 = 0.f;
        #pragma unroll
        for (int k = 0; k < LL; k++){
            a0 += Wgd[i*LL + k] * Wid[k*L3 + j];
            a1 += Wgc[i*LL + k] * Wic[k*L3 + j];
        }
        g_Wcd[o] = a0;
        g_Wcc[o] = a1;
    }
    for (int v = tid; v < VV; v += 1024) sdeg[v] = 0;
    __syncthreads();
    for (int e = tid; e < EE; e += 1024) atomicAdd(&sdeg[ei[EE+e]], 1);
    __syncthreads();
    if (tid == 0){
        int acc = 0;
        g_rowptr[0] = 0;
        for (int v = 0; v < VV; v++){ scur[v] = acc; acc += sdeg[v]; g_rowptr[v+1] = acc; }
    }
    __syncthreads();
    for (int e = tid; e < EE; e += 1024){
        int pos = atomicAdd(&scur[ei[EE+e]], 1);
        g_eid[pos] = e;
    }
    __syncthreads();
    for (int v = tid; v < VV; v += 1024){
        int s = g_rowptr[v], e = g_rowptr[v+1];
        for (int i = s+1; i < e; i++){
            int key = g_eid[i]; int k = i-1;
            while (k >= s && g_eid[k] > key){ g_eid[k+1] = g_eid[k]; k--; }
            g_eid[k+1] = key;
        }
        for (int i = s; i < e; i++){
            int id = g_eid[i];
            g_cols[i] = ei[id];
            g_vals[i] = attr[id];
        }
    }
}

// ---------------- encoder ----------------
__global__ void k_encode(const float* __restrict__ x, const float* __restrict__ W,
                         const float* __restrict__ b){
    __shared__ float xs[CC*32];
    __shared__ float Ws[CC*LL];
    __shared__ float bs[LL];
    int blk = blockIdx.x;
    int nv = blk / 5;
    int t0 = (blk % 5) * 32;
    int tid = threadIdx.x;
    for (int i = tid; i < CC*32; i += 256){
        int c = i / 32, tl = i % 32, t = t0 + tl;
        xs[c*32 + tl] = (t < TT) ? x[((size_t)nv*CC + c)*TT + t] : 0.f;
    }
    for (int i = tid; i < CC*LL; i += 256) Ws[i] = W[i];
    if (tid < LL) bs[tid] = b[tid];
    __syncthreads();
    int l = tid & 63, tg = tid >> 6;
    for (int tl = tg; tl < 32; tl += 4){
        int t = t0 + tl;
        if (t >= TT) break;
        float acc = bs[l];
        #pragma unroll
        for (int c = 0; c < CC; c++) acc += xs[c*32 + tl] * Ws[c*LL + l];
        g_xe[((size_t)t*NV + nv)*LL + l] = acc;
    }
}

// ---------------- gather: agg = S.xe, 4-way edge unroll (MLP 1 -> 4+) ----------------
__global__ void __launch_bounds__(256) k_agg(){
    int b = blockIdx.x;
    int t   = b >> 7;
    int rem = b & 127;
    int n   = rem >> 4;
    int v0  = (rem & 15) * 128;
    int tid = threadIdx.x;
    const float* xb = g_xe  + ((size_t)t*NV + (size_t)n*VV) * LL;
    float*       ob = g_agg + ((size_t)t*NV + (size_t)n*VV + v0) * LL;
    int lane = tid & 63, rg = tid >> 6;
    for (int r = rg; r < 128; r += 4){
        int v = v0 + r;
        int s = g_rowptr[v], e = g_rowptr[v+1];
        float a0 = 0.f, a1 = 0.f, a2 = 0.f, a3 = 0.f;
        int idx = s;
        for (; idx + 4 <= e; idx += 4){
            int   c0 = g_cols[idx  ], c1 = g_cols[idx+1];
            int   c2 = g_cols[idx+2], c3 = g_cols[idx+3];
            float w0 = g_vals[idx  ], w1 = g_vals[idx+1];
            float w2 = g_vals[idx+2], w3 = g_vals[idx+3];
            a0 += xb[(size_t)c0*LL + lane] * w0;
            a1 += xb[(size_t)c1*LL + lane] * w1;
            a2 += xb[(size_t)c2*LL + lane] * w2;
            a3 += xb[(size_t)c3*LL + lane] * w3;
        }
        float acc = (a0 + a1) + (a2 + a3);   // fixed tree: deterministic
        for (; idx < e; idx++)
            acc += xb[(size_t)g_cols[idx]*LL + lane] * g_vals[idx];
        ob[(size_t)r*LL + lane] = acc;
    }
}

// ---------------- fused persistent domain scan: gi-GEMM + GRU, 150 steps -------------
// grid 128 (128 rows/block), 512 threads, dyn smem 164608 (1 block/SM, single wave)
__global__ void __launch_bounds__(512) k_domscan(const float* __restrict__ Wh,
                                                 const float* __restrict__ bias){
    extern __shared__ float sm[];
    float* Wst = sm;                 // [128][192]: rows0-63 = Wh, rows64-127 = Wcd
    float* hs  = Wst + 128*L3;       // [128][64]
    float* ags = hs + 128*LL;        // [128][64]
    float* bs  = ags + 128*LL;       // [192]
    int tid = threadIdx.x;
    int row0 = blockIdx.x * 128;
    for (int i = tid; i < (64*L3)/4; i += 512){
        ((float4*)Wst)[i]           = ((const float4*)Wh)[i];
        ((float4*)(Wst + 64*L3))[i] = ((const float4*)g_Wcd)[i];
    }
    for (int i = tid; i < 128*LL; i += 512) hs[i] = 0.f;
    if (tid < L3) bs[tid] = bias[tid];
    // preload agg tile for t=0
    {
        const float4* src = (const float4*)(g_agg + (size_t)row0*LL);
        #pragma unroll
        for (int j = 0; j < 4; j++) ((float4*)ags)[tid + j*512] = src[tid + j*512];
    }
    __syncthreads();

    int r0 = (tid >> 4) * 4, c0 = (tid & 15) * 4;

    for (int t = 0; t < TT; t++){
        // prefetch next agg tile into registers (hidden under this step's GEMM)
        float4 pf[4];
        if (t + 1 < TT){
            const float4* src = (const float4*)(g_agg + ((size_t)(t+1)*NV + row0)*LL);
            #pragma unroll
            for (int j = 0; j < 4; j++) pf[j] = src[tid + j*512];
        }

        u64 az[4][2], ar[4][2], anh[4][2], ang[4][2];
        {
            const u64* bz = (const u64*)(bs + c0);
            const u64* br = (const u64*)(bs + 64 + c0);
            const u64* bn = (const u64*)(bs + 128 + c0);
            u64 z0=bz[0], z1=bz[1], q0=br[0], q1=br[1], n0=bn[0], n1=bn[1];
            #pragma unroll
            for (int i=0;i<4;i++){ az[i][0]=z0; az[i][1]=z1; ar[i][0]=q0; ar[i][1]=q1;
                                   ang[i][0]=n0; ang[i][1]=n1; anh[i][0]=0ull; anh[i][1]=0ull; }
        }
        // part 1: h @ Wh (W rows 0..63); n-gate -> anh
        #pragma unroll 2
        for (int k0 = 0; k0 < 64; k0 += 4){
            float4 a[4];
            #pragma unroll
            for (int i=0;i<4;i++) a[i] = *(const float4*)(hs + (r0+i)*LL + k0);
            #pragma unroll
            for (int kk=0; kk<4; kk++){
                const float* wrow = Wst + (k0+kk)*L3;
                const u64* wz = (const u64*)(wrow + c0);
                const u64* wr = (const u64*)(wrow + 64 + c0);
                const u64* wn = (const u64*)(wrow + 128 + c0);
                u64 wz0=wz[0],wz1=wz[1],wr0=wr[0],wr1=wr[1],wn0=wn[0],wn1=wn[1];
                #pragma unroll
                for (int i=0;i<4;i++){
                    float av = (kk==0)?a[i].x:(kk==1)?a[i].y:(kk==2)?a[i].z:a[i].w;
                    u64 ad = f2dup(av);
                    az [i][0]=f2fma(ad,wz0,az [i][0]); az [i][1]=f2fma(ad,wz1,az [i][1]);
                    ar [i][0]=f2fma(ad,wr0,ar [i][0]); ar [i][1]=f2fma(ad,wr1,ar [i][1]);
                    anh[i][0]=f2fma(ad,wn0,anh[i][0]); anh[i][1]=f2fma(ad,wn1,anh[i][1]);
                }
            }
        }
        // part 2: agg @ Wcd (W rows 64..127); n-gate -> ang
        #pragma unroll 2
        for (int k0 = 0; k0 < 64; k0 += 4){
            float4 a[4];
            #pragma unroll
            for (int i=0;i<4;i++) a[i] = *(const float4*)(ags + (r0+i)*LL + k0);
            #pragma unroll
            for (int kk=0; kk<4; kk++){
                const float* wrow = Wst + (64 + k0 + kk)*L3;
                const u64* wz = (const u64*)(wrow + c0);
                const u64* wr = (const u64*)(wrow + 64 + c0);
                const u64* wn = (const u64*)(wrow + 128 + c0);
                u64 wz0=wz[0],wz1=wz[1],wr0=wr[0],wr1=wr[1],wn0=wn[0],wn1=wn[1];
                #pragma unroll
                for (int i=0;i<4;i++){
                    float av = (kk==0)?a[i].x:(kk==1)?a[i].y:(kk==2)?a[i].z:a[i].w;
                    u64 ad = f2dup(av);
                    az [i][0]=f2fma(ad,wz0,az [i][0]); az [i][1]=f2fma(ad,wz1,az [i][1]);
                    ar [i][0]=f2fma(ad,wr0,ar [i][0]); ar [i][1]=f2fma(ad,wr1,ar [i][1]);
                    ang[i][0]=f2fma(ad,wn0,ang[i][0]); ang[i][1]=f2fma(ad,wn1,ang[i][1]);
                }
            }
        }
        __syncthreads();   // all reads of hs/ags complete before hs writes / ags overwrite
        // store prefetched next tile into ags (readers done)
        if (t + 1 < TT){
            #pragma unroll
            for (int j = 0; j < 4; j++) ((float4*)ags)[tid + j*512] = pf[j];
        }
        #pragma unroll
        for (int i=0;i<4;i++){
            int r = r0 + i;
            float2 vz0=f2unpk(az[i][0]),  vz1=f2unpk(az[i][1]);
            float2 vr0=f2unpk(ar[i][0]),  vr1=f2unpk(ar[i][1]);
            float2 vh0=f2unpk(anh[i][0]), vh1=f2unpk(anh[i][1]);
            float2 vg0=f2unpk(ang[i][0]), vg1=f2unpk(ang[i][1]);
            float zz[4]={vz0.x,vz0.y,vz1.x,vz1.y};
            float rv[4]={vr0.x,vr0.y,vr1.x,vr1.y};
            float nh[4]={vh0.x,vh0.y,vh1.x,vh1.y};
            float ng[4]={vg0.x,vg0.y,vg1.x,vg1.y};
            #pragma unroll
            for (int j=0;j<4;j++){
                float z  = fsigm(zz[j]);
                float rg = fsigm(rv[j]);
                float nn = ftanh(ng[j] + rg*nh[j]);
                float hp = hs[r*LL + c0 + j];
                hs[r*LL + c0 + j] = (1.f-z)*nn + z*hp;
            }
        }
        __syncthreads();
    }
    for (int i = tid; i < 128*LL; i += 512) g_hd[(size_t)row0*LL + i] = hs[i];
}

// ---------------- domain MLP + cz precompute ----------------
__global__ void k_dommlp(const float* __restrict__ Wd1, const float* __restrict__ bd1,
                         const float* __restrict__ Wd2, const float* __restrict__ bd2,
                         const float* __restrict__ odeW1, const float* __restrict__ odeb1){
    extern __shared__ float sm[];
    float* W1s = sm;
    float* W2s = W1s + 4096;
    float* Wzs = W2s + 4096;
    float* hds = Wzs + 4096;
    float* t1s = hds + 1024;
    float* zDs = t1s + 1024;
    float* b1s = zDs + 1024;
    float* b2s = b1s + 64;
    float* bos = b2s + 64;
    int tid = threadIdx.x;
    int row0 = blockIdx.x * 16;
    for (int i = tid; i < 4096; i += 256){ W1s[i] = Wd1[i]; W2s[i] = Wd2[i]; Wzs[i] = odeW1[4096 + i]; }
    for (int i = tid; i < 16*LL; i += 256) hds[i] = g_hd[(size_t)row0*LL + i];
    if (tid < 64){ b1s[tid] = bd1[tid]; b2s[tid] = bd2[tid]; bos[tid] = odeb1[tid]; }
    __syncthreads();
    int j = tid & 63, rg = tid >> 6;
    for (int r = rg; r < 16; r += 4){
        float acc = b1s[j];
        #pragma unroll
        for (int k = 0; k < LL; k++) acc += hds[r*LL + k] * W1s[k*LL + j];
        t1s[r*LL + j] = ftanh(acc);
    }
    __syncthreads();
    for (int r = rg; r < 16; r += 4){
        float acc = b2s[j];
        #pragma unroll
        for (int k = 0; k < LL; k++) acc += t1s[r*LL + k] * W2s[k*LL + j];
        zDs[r*LL + j] = acc;
    }
    __syncthreads();
    for (int r = rg; r < 16; r += 4){
        float acc = bos[j];
        #pragma unroll
        for (int k = 0; k < LL; k++) acc += zDs[r*LL + k] * Wzs[k*LL + j];
        g_cz[(size_t)(row0+r)*LL + j] = acc;
    }
}

// ---------------- fused persistent correction scan: ODE + gi-GEMM + GRU, 149 steps ----
// grid 128 (128 rows/block), 512 threads, dyn smem 230400 (1 block/SM, single wave)
__global__ void __launch_bounds__(512) k_corrscan(const float* __restrict__ odeW1,
        const float* __restrict__ odeW2, const float* __restrict__ odeb2,
        const float* __restrict__ Wh, const float* __restrict__ bias){
    extern __shared__ float sm[];
    float* Wst = sm;               // [128][192]: rows0-63 = Wh, rows64-127 = Wcc
    float* W1s = Wst + 128*L3;     // [64][64]
    float* W2s = W1s + 4096;       // [64][64]
    float* hs  = W2s + 4096;       // [128][64]
    float* hos = hs  + 128*LL;     // [128][64]
    float* Xs  = hos + 128*LL;     // [128][64]  t1 buffer, then agg tile (time-shared)
    float* bs  = Xs  + 128*LL;     // [192]
    float* b2s = bs + L3;          // [64]
    int tid = threadIdx.x;
    int row0 = blockIdx.x * 128;
    for (int i = tid; i < (64*L3)/4; i += 512){
        ((float4*)Wst)[i]           = ((const float4*)Wh)[i];
        ((float4*)(Wst + 64*L3))[i] = ((const float4*)g_Wcc)[i];
    }
    for (int i = tid; i < 1024; i += 512){ ((float4*)W1s)[i] = ((const float4*)odeW1)[i];
                                           ((float4*)W2s)[i] = ((const float4*)odeW2)[i]; }
    for (int i = tid; i < (128*LL)/4; i += 512)
        ((float4*)hs)[i] = ((const float4*)(g_xe + (size_t)row0*LL))[i];   // h0 = xe[0]
    if (tid < L3) bs[tid] = bias[tid];
    if (tid < 64) b2s[tid] = odeb2[tid];
    __syncthreads();

    int p_r0 = (tid >> 3) * 2, p_c0 = (tid & 7) * 8;    // phase1/2: 2 rows x 8 cols
    int g_r0 = (tid >> 4) * 4, g_c0 = (tid & 15) * 4;   // phase3:   4 rows x 4 cols/gate
    const float* czp = g_cz + (size_t)row0 * LL;

    // cz is loop-invariant: load ONCE into registers
    float4 cz00 = __ldg((const float4*)(czp + (size_t)(p_r0+0)*LL + p_c0));
    float4 cz01 = __ldg((const float4*)(czp + (size_t)(p_r0+0)*LL + p_c0 + 4));
    float4 cz10 = __ldg((const float4*)(czp + (size_t)(p_r0+1)*LL + p_c0));
    float4 cz11 = __ldg((const float4*)(czp + (size_t)(p_r0+1)*LL + p_c0 + 4));
    float czf[2][8] = {{cz00.x,cz00.y,cz00.z,cz00.w, cz01.x,cz01.y,cz01.z,cz01.w},
                       {cz10.x,cz10.y,cz10.z,cz10.w, cz11.x,cz11.y,cz11.z,cz11.w}};

    for (int t = 1; t < TT; t++){
        // prefetch this step's agg tile into registers (hidden under phases 1-2)
        float4 pf[4];
        {
            const float4* src = (const float4*)(g_agg + ((size_t)t*NV + row0)*LL);
            #pragma unroll
            for (int j = 0; j < 4; j++) pf[j] = src[tid + j*512];
        }

        // phase1: Xs(t1) = tanh(hs @ W1 + cz)
        {
            u64 acc[2][4];
            #pragma unroll
            for (int i=0;i<2;i++){ acc[i][0]=0ull; acc[i][1]=0ull; acc[i][2]=0ull; acc[i][3]=0ull; }
            #pragma unroll 4
            for (int k0 = 0; k0 < 64; k0 += 4){
                float4 a0 = *(const float4*)(hs + (p_r0+0)*LL + k0);
                float4 a1 = *(const float4*)(hs + (p_r0+1)*LL + k0);
                #pragma unroll
                for (int kk=0; kk<4; kk++){
                    const u64* wp = (const u64*)(W1s + (k0+kk)*LL + p_c0);
                    u64 w0=wp[0], w1=wp[1], w2=wp[2], w3=wp[3];
                    float v0 = (kk==0)?a0.x:(kk==1)?a0.y:(kk==2)?a0.z:a0.w;
                    float v1 = (kk==0)?a1.x:(kk==1)?a1.y:(kk==2)?a1.z:a1.w;
                    u64 d0 = f2dup(v0), d1 = f2dup(v1);
                    acc[0][0]=f2fma(d0,w0,acc[0][0]); acc[0][1]=f2fma(d0,w1,acc[0][1]);
                    acc[0][2]=f2fma(d0,w2,acc[0][2]); acc[0][3]=f2fma(d0,w3,acc[0][3]);
                    acc[1][0]=f2fma(d1,w0,acc[1][0]); acc[1][1]=f2fma(d1,w1,acc[1][1]);
                    acc[1][2]=f2fma(d1,w2,acc[1][2]); acc[1][3]=f2fma(d1,w3,acc[1][3]);
                }
            }
            #pragma unroll
            for (int i=0;i<2;i++)
                #pragma unroll
                for (int p=0;p<4;p++){
                    float2 v = f2unpk(acc[i][p]);
                    Xs[(p_r0+i)*LL + p_c0 + 2*p    ] = ftanh(v.x + czf[i][2*p  ]);
                    Xs[(p_r0+i)*LL + p_c0 + 2*p + 1] = ftanh(v.y + czf[i][2*p+1]);
                }
        }
        __syncthreads();
        // phase2: hos = hs + Xs @ W2 + b2
        {
            u64 acc[2][4];
            {
                const u64* bp = (const u64*)(b2s + p_c0);
                u64 b0=bp[0], b1=bp[1], b2v=bp[2], b3=bp[3];
                acc[0][0]=b0; acc[0][1]=b1; acc[0][2]=b2v; acc[0][3]=b3;
                acc[1][0]=b0; acc[1][1]=b1; acc[1][2]=b2v; acc[1][3]=b3;
            }
            #pragma unroll 4
            for (int k0 = 0; k0 < 64; k0 += 4){
                float4 a0 = *(const float4*)(Xs + (p_r0+0)*LL + k0);
                float4 a1 = *(const float4*)(Xs + (p_r0+1)*LL + k0);
                #pragma unroll
                for (int kk=0; kk<4; kk++){
                    const u64* wp = (const u64*)(W2s + (k0+kk)*LL + p_c0);
                    u64 w0=wp[0], w1=wp[1], w2=wp[2], w3=wp[3];
                    float v0 = (kk==0)?a0.x:(kk==1)?a0.y:(kk==2)?a0.z:a0.w;
                    float v1 = (kk==0)?a1.x:(kk==1)?a1.y:(kk==2)?a1.z:a1.w;
                    u64 d0 = f2dup(v0), d1 = f2dup(v1);
                    acc[0][0]=f2fma(d0,w0,acc[0][0]); acc[0][1]=f2fma(d0,w1,acc[0][1]);
                    acc[0][2]=f2fma(d0,w2,acc[0][2]); acc[0][3]=f2fma(d0,w3,acc[0][3]);
                    acc[1][0]=f2fma(d1,w0,acc[1][0]); acc[1][1]=f2fma(d1,w1,acc[1][1]);
                    acc[1][2]=f2fma(d1,w2,acc[1][2]); acc[1][3]=f2fma(d1,w3,acc[1][3]);
                }
            }
            #pragma unroll
            for (int i=0;i<2;i++)
                #pragma unroll
                for (int p=0;p<4;p++){
                    float2 v = f2unpk(acc[i][p]);
                    int base = (p_r0+i)*LL + p_c0 + 2*p;
                    hos[base    ] = hs[base    ] + v.x;
                    hos[base + 1] = hs[base + 1] + v.y;
                }
        }
        __syncthreads();
        // store prefetched agg tile into Xs (t1 dead; phase2 readers done)
        #pragma unroll
        for (int j = 0; j < 4; j++) ((float4*)Xs)[tid + j*512] = pf[j];
        __syncthreads();
        // phase3: GRU stacked-K GEMM: A = [hos | agg], n-gate split
        u64 az[4][2], ar[4][2], anh[4][2], ang[4][2];
        {
            const u64* bz = (const u64*)(bs + g_c0);
            const u64* br = (const u64*)(bs + 64 + g_c0);
            const u64* bn = (const u64*)(bs + 128 + g_c0);
            u64 z0=bz[0], z1=bz[1], q0=br[0], q1=br[1], n0=bn[0], n1=bn[1];
            #pragma unroll
            for (int i=0;i<4;i++){ az[i][0]=z0; az[i][1]=z1; ar[i][0]=q0; ar[i][1]=q1;
                                   ang[i][0]=n0; ang[i][1]=n1; anh[i][0]=0ull; anh[i][1]=0ull; }
        }
        #pragma unroll 2
        for (int k0 = 0; k0 < 64; k0 += 4){
            float4 a[4];
            #pragma unroll
            for (int i=0;i<4;i++) a[i] = *(const float4*)(hos + (g_r0+i)*LL + k0);
            #pragma unroll
            for (int kk=0; kk<4; kk++){
                const float* wrow = Wst + (k0+kk)*L3;
                const u64* wz = (const u64*)(wrow + g_c0);
                const u64* wr = (const u64*)(wrow + 64 + g_c0);
                const u64* wn = (const u64*)(wrow + 128 + g_c0);
                u64 wz0=wz[0],wz1=wz[1],wr0=wr[0],wr1=wr[1],wn0=wn[0],wn1=wn[1];
                #pragma unroll
                for (int i=0;i<4;i++){
                    float av = (kk==0)?a[i].x:(kk==1)?a[i].y:(kk==2)?a[i].z:a[i].w;
                    u64 ad = f2dup(av);
                    az [i][0]=f2fma(ad,wz0,az [i][0]); az [i][1]=f2fma(ad,wz1,az [i][1]);
                    ar [i][0]=f2fma(ad,wr0,ar [i][0]); ar [i][1]=f2fma(ad,wr1,ar [i][1]);
                    anh[i][0]=f2fma(ad,wn0,anh[i][0]); anh[i][1]=f2fma(ad,wn1,anh[i][1]);
                }
            }
        }
        #pragma unroll 2
        for (int k0 = 0; k0 < 64; k0 += 4){
            float4 a[4];
            #pragma unroll
            for (int i=0;i<4;i++) a[i] = *(const float4*)(Xs + (g_r0+i)*LL + k0);
            #pragma unroll
            for (int kk=0; kk<4; kk++){
                const float* wrow = Wst + (64 + k0 + kk)*L3;
                const u64* wz = (const u64*)(wrow + g_c0);
                const u64* wr = (const u64*)(wrow + 64 + g_c0);
                const u64* wn = (const u64*)(wrow + 128 + g_c0);
                u64 wz0=wz[0],wz1=wz[1],wr0=wr[0],wr1=wr[1],wn0=wn[0],wn1=wn[1];
                #pragma unroll
                for (int i=0;i<4;i++){
                    float av = (kk==0)?a[i].x:(kk==1)?a[i].y:(kk==2)?a[i].z:a[i].w;
                    u64 ad = f2dup(av);
                    az [i][0]=f2fma(ad,wz0,az [i][0]); az [i][1]=f2fma(ad,wz1,az [i][1]);
                    ar [i][0]=f2fma(ad,wr0,ar [i][0]); ar [i][1]=f2fma(ad,wr1,ar [i][1]);
                    ang[i][0]=f2fma(ad,wn0,ang[i][0]); ang[i][1]=f2fma(ad,wn1,ang[i][1]);
                }
            }
        }
        // NO sync needed: phase3 GEMM reads hos/Xs; gates write hs/g_xe only
        #pragma unroll
        for (int i=0;i<4;i++){
            int r = g_r0 + i;
            float2 vz0=f2unpk(az[i][0]),  vz1=f2unpk(az[i][1]);
            float2 vr0=f2unpk(ar[i][0]),  vr1=f2unpk(ar[i][1]);
            float2 vh0=f2unpk(anh[i][0]), vh1=f2unpk(anh[i][1]);
            float2 vg0=f2unpk(ang[i][0]), vg1=f2unpk(ang[i][1]);
            float zz[4]={vz0.x,vz0.y,vz1.x,vz1.y};
            float rv[4]={vr0.x,vr0.y,vr1.x,vr1.y};
            float nh[4]={vh0.x,vh0.y,vh1.x,vh1.y};
            float ng[4]={vg0.x,vg0.y,vg1.x,vg1.y};
            float hn4[4];
            #pragma unroll
            for (int j=0;j<4;j++){
                float z  = fsigm(zz[j]);
                float rg = fsigm(rv[j]);
                float nn = ftanh(ng[j] + rg*nh[j]);
                float ho = hos[r*LL + g_c0 + j];
                hn4[j] = (1.f-z)*nn + z*ho;
            }
            #pragma unroll
            for (int j=0;j<4;j++) hs[r*LL + g_c0 + j] = hn4[j];
            *(float4*)(g_xe + ((size_t)t*NV + row0 + r)*LL + g_c0)
                = make_float4(hn4[0], hn4[1], hn4[2], hn4[3]);
        }
        __syncthreads();   // hs writes + Xs reads complete before next iteration
    }
}

// ---------------- decoder ----------------
__global__ void k_decode(float* __restrict__ out, const float* __restrict__ W,
                         const float* __restrict__ b){
    __shared__ float zs[32*65];
    __shared__ float Ws[LL*CC];
    __shared__ float bs[CC];
    int blk = blockIdx.x;
    int nv = blk / 5;
    int t0 = (blk % 5) * 32;
    int tid = threadIdx.x;
    for (int i = tid; i < 32*LL; i += 256){
        int tl = i >> 6, l = i & 63, t = t0 + tl;
        zs[tl*65 + l] = (t < TT) ? g_xe[((size_t)t*NV + nv)*LL + l] : 0.f;
    }
    for (int i = tid; i < LL*CC; i += 256) Ws[i] = W[i];
    if (tid < CC) bs[tid] = b[tid];
    __syncthreads();
    for (int o = tid; o < 512; o += 256){
        int c = o >> 5, tl = o & 31, t = t0 + tl;
        if (t >= TT) continue;
        float acc = bs[c];
        #pragma unroll
        for (int l = 0; l < LL; l++) acc += zs[tl*65 + l] * Ws[l*CC + c];
        out[((size_t)nv*CC + c)*TT + t] = acc;
    }
}

// ---------------- launch ----------------
extern "C" void kernel_launch(void* const* d_in, const int* in_sizes, int n_in,
                              void* d_out, int out_size){
    const float* x      = (const float*)d_in[0];
    const int*   ei     = (const int*)  d_in[1];
    const float* attr   = (const float*)d_in[2];
    const float* W_enc  = (const float*)d_in[3];
    const float* b_enc  = (const float*)d_in[4];
    const float* W_gd   = (const float*)d_in[5];
    const float* gd_Wi  = (const float*)d_in[6];
    const float* gd_Wh  = (const float*)d_in[7];
    const float* gd_b   = (const float*)d_in[8];
    const float* W_dom1 = (const float*)d_in[9];
    const float* b_dom1 = (const float*)d_in[10];
    const float* W_dom2 = (const float*)d_in[11];
    const float* b_dom2 = (const float*)d_in[12];
    const float* ode_W1 = (const float*)d_in[13];
    const float* ode_b1 = (const float*)d_in[14];
    const float* ode_W2 = (const float*)d_in[15];
    const float* ode_b2 = (const float*)d_in[16];
    const float* W_gc   = (const float*)d_in[17];
    const float* gc_Wi  = (const float*)d_in[18];
    const float* gc_Wh  = (const float*)d_in[19];
    const float* gc_b   = (const float*)d_in[20];
    const float* W_dec  = (const float*)d_in[21];
    const float* b_dec  = (const float*)d_in[22];
    float* out = (float*)d_out;

    const int SM_DOMS  = (128*L3 + 2*128*LL + L3) * 4;                         // 164608
    const int SM_CORRS = (128*L3 + 4096 + 4096 + 3*128*LL + L3 + 64) * 4;      // 230400
    const int SM_MLP   = (3*4096 + 3*1024 + 3*64) * 4;                         // 62208

    cudaFuncSetAttribute(k_domscan,  cudaFuncAttributeMaxDynamicSharedMemorySize, SM_DOMS);
    cudaFuncSetAttribute(k_corrscan, cudaFuncAttributeMaxDynamicSharedMemorySize, SM_CORRS);
    cudaFuncSetAttribute(k_dommlp,   cudaFuncAttributeMaxDynamicSharedMemorySize, SM_MLP);

    // 1: CSR build + weight folding (one block)
    k_csrfold<<<1, 1024>>>(ei, attr, W_gd, gd_Wi, W_gc, gc_Wi);
    // 2: encoder
    k_encode<<<NV*5, 256>>>(x, W_enc, b_enc);
    // 3: gather ONCE (4-way edge unroll)
    k_agg <<<TT*128, 256>>>();
    // 4: fused persistent domain scan (R14 structure)  <-- ncu capture slot
    k_domscan<<<NV/128, 512, SM_DOMS>>>(gd_Wh, gd_b);
    // 5: domain MLP + cz
    k_dommlp<<<NV/16, 256, SM_MLP>>>(W_dom1, b_dom1, W_dom2, b_dom2, ode_W1, ode_b1);
    // 6: fused persistent correction scan (R14 structure)
    k_corrscan<<<NV/128, 512, SM_CORRS>>>(ode_W1, ode_W2, ode_b2, gc_Wh, gc_b);
    // 7: decoder
    k_decode<<<NV*5, 256>>>(out, W_dec, b_dec);
}